// round 1
// baseline (speedup 1.0000x reference)
#include <cuda_runtime.h>
#include <math.h>
#include <stdint.h>

// Problem constants
#define HSZ 512
#define ESZ 256
#define LSZ 64
#define OSZ 2
#define NH  4
#define HD  128   // HSZ/NH
#define BSN 1024
#define SS  100
#define TT  30

// ---------------------------------------------------------------------------
// Scratch (device globals; no allocations allowed)
// ---------------------------------------------------------------------------
__device__ float g_K[(size_t)BSN * NH * HD * SS];   // [b,h,d,s]  (transposed)
__device__ float g_V[(size_t)BSN * NH * SS * HD];   // [b,h,s,d]
__device__ float g_q[BSN * HSZ];
__device__ float g_att[BSN * HSZ];
__device__ float g_attproj[BSN * HSZ];
__device__ float g_fc1[BSN * HSZ];
__device__ float g_gates[BSN * 4 * HSZ];
__device__ float g_h1[BSN * HSZ];
__device__ float g_c1[BSN * HSZ];
__device__ float g_h2[BSN * HSZ];   // doubles as att_in (carry = h2)
__device__ float g_c2[BSN * HSZ];
__device__ float g_y1[BSN * (HSZ / 2)];
__device__ float g_y2[BSN * (HSZ / 4)];

// ---------------------------------------------------------------------------
// Generic SGEMM:  C = act( A1 @ W1^T [+ A2 @ W2^T] + b1 [+ b2] )
// A row-major [M,K], W row-major [N,K].  BM=128, BN=64, BK=16, 256 thr, 8x4/thr.
// M % 128 == 0, N % 64 == 0, K % 16 == 0 for all call sites.
// EPI: 0 plain, 1 leaky-relu(0.2), 2 scale, 3 K-layout write, 4 V-layout write
// ---------------------------------------------------------------------------
template <int EPI>
__global__ __launch_bounds__(256)
void gemm_kernel(const float* __restrict__ A1, int lda1, int K1,
                 const float* __restrict__ W1, int ldw1,
                 const float* __restrict__ A2, int lda2, int K2,
                 const float* __restrict__ W2, int ldw2,
                 const float* __restrict__ b1, const float* __restrict__ b2,
                 float* __restrict__ C, int N, float scale)
{
    constexpr int BM = 128, BN = 64, BK = 16;
    __shared__ float As[BK][BM];
    __shared__ float Ws[BK][BN];

    const int tid = threadIdx.x;
    const int tr = tid >> 4;          // 0..15  (row group of 8)
    const int tc = tid & 15;          // 0..15  (col group of 4)
    const int m0 = blockIdx.y * BM;
    const int n0 = blockIdx.x * BN;

    float acc[8][4];
#pragma unroll
    for (int i = 0; i < 8; i++)
#pragma unroll
        for (int j = 0; j < 4; j++) acc[i][j] = 0.f;

    const int lr  = tid >> 2;         // 0..63
    const int lc  = (tid & 3) * 4;    // 0,4,8,12

#pragma unroll 1
    for (int pass = 0; pass < 2; ++pass) {
        const float* A = pass ? A2 : A1;
        const float* W = pass ? W2 : W1;
        const int lda = pass ? lda2 : lda1;
        const int ldw = pass ? ldw2 : ldw1;
        const int K   = pass ? K2 : K1;
        if (K == 0) continue;

        for (int k0 = 0; k0 < K; k0 += BK) {
            // A tile: 128 x 16  (2 float4 per thread), store transposed
#pragma unroll
            for (int rep = 0; rep < 2; ++rep) {
                int row = lr + rep * 64;
                float4 v = *reinterpret_cast<const float4*>(
                    A + (size_t)(m0 + row) * lda + k0 + lc);
                As[lc + 0][row] = v.x; As[lc + 1][row] = v.y;
                As[lc + 2][row] = v.z; As[lc + 3][row] = v.w;
            }
            // W tile: 64 x 16 (1 float4 per thread), store transposed
            {
                float4 v = *reinterpret_cast<const float4*>(
                    W + (size_t)(n0 + lr) * ldw + k0 + lc);
                Ws[lc + 0][lr] = v.x; Ws[lc + 1][lr] = v.y;
                Ws[lc + 2][lr] = v.z; Ws[lc + 3][lr] = v.w;
            }
            __syncthreads();

#pragma unroll
            for (int kk = 0; kk < BK; ++kk) {
                float4 a0 = *reinterpret_cast<const float4*>(&As[kk][tr * 8]);
                float4 a1 = *reinterpret_cast<const float4*>(&As[kk][tr * 8 + 4]);
                float4 w  = *reinterpret_cast<const float4*>(&Ws[kk][tc * 4]);
                float am[8] = {a0.x, a0.y, a0.z, a0.w, a1.x, a1.y, a1.z, a1.w};
                float wn[4] = {w.x, w.y, w.z, w.w};
#pragma unroll
                for (int i = 0; i < 8; i++)
#pragma unroll
                    for (int j = 0; j < 4; j++)
                        acc[i][j] += am[i] * wn[j];
            }
            __syncthreads();
        }
    }

    // epilogue
#pragma unroll
    for (int i = 0; i < 8; i++) {
        int m = m0 + tr * 8 + i;
#pragma unroll
        for (int j = 0; j < 4; j++) {
            int n = n0 + tc * 4 + j;
            float v = acc[i][j];
            if (b1) v += b1[n];
            if (b2) v += b2[n];
            if (EPI == 1) v = (v >= 0.f) ? v : 0.2f * v;
            if (EPI == 2) v *= scale;
            if (EPI <= 2) {
                C[(size_t)m * N + n] = v;
            } else {
                int b = m / SS, s = m - b * SS;
                if (EPI == 3) {
                    // K: [b, h, d, s] -> b*H*S + n*S + s
                    C[(size_t)b * HSZ * SS + (size_t)n * SS + s] = v;
                } else {
                    // V: [b, h, s, d]
                    int h = n >> 7, d = n & 127;
                    C[(size_t)b * HSZ * SS + (size_t)h * SS * HD + (size_t)s * HD + d] = v;
                }
            }
        }
    }
}

// ---------------------------------------------------------------------------
// Attention: one block per (b,h). q already scaled. K transposed [d,s], V [s,d].
// ---------------------------------------------------------------------------
__global__ __launch_bounds__(128)
void attn_kernel(const float* __restrict__ q, const float* __restrict__ Kt,
                 const float* __restrict__ V, float* __restrict__ att)
{
    __shared__ float qs[HD];
    __shared__ float sc[128];
    __shared__ float red[128];

    const int bh = blockIdx.x;
    const int b = bh >> 2, h = bh & 3;
    const int tid = threadIdx.x;

    qs[tid] = q[(size_t)b * HSZ + h * HD + tid];
    __syncthreads();

    // scores[s] = q . K[:,s]
    float a = 0.f;
    const float* Kp = Kt + (size_t)bh * HD * SS;
    if (tid < SS) {
#pragma unroll 8
        for (int d = 0; d < HD; ++d) a += qs[d] * Kp[d * SS + tid];
    }
    sc[tid] = a;
    red[tid] = (tid < SS) ? a : -1e30f;
    __syncthreads();
#pragma unroll
    for (int off = 64; off > 0; off >>= 1) {
        if (tid < off) red[tid] = fmaxf(red[tid], red[tid + off]);
        __syncthreads();
    }
    const float mx = red[0];
    __syncthreads();

    float e = (tid < SS) ? expf(sc[tid] - mx) : 0.f;
    sc[tid] = e;
    red[tid] = e;
    __syncthreads();
#pragma unroll
    for (int off = 64; off > 0; off >>= 1) {
        if (tid < off) red[tid] += red[tid + off];
        __syncthreads();
    }
    const float inv = 1.f / red[0];

    // att[d] = sum_s w[s] * V[s,d]
    float o = 0.f;
    const float* Vp = V + (size_t)bh * SS * HD + tid;
#pragma unroll 4
    for (int s = 0; s < SS; ++s) o += sc[s] * Vp[(size_t)s * HD];
    att[(size_t)b * HSZ + h * HD + tid] = o * inv;
}

// ---------------------------------------------------------------------------
// LSTM pointwise: gates [BS, 4H] (i,f,g,o) -> h,c in place
// ---------------------------------------------------------------------------
__global__ void lstm_pw(const float* __restrict__ g,
                        float* __restrict__ h, float* __restrict__ c)
{
    int idx = blockIdx.x * blockDim.x + threadIdx.x;   // BS*H threads
    int m = idx >> 9;
    int n = idx & 511;
    const float* gr = g + (size_t)m * (4 * HSZ);
    float i  = 1.f / (1.f + expf(-gr[n]));
    float f  = 1.f / (1.f + expf(-gr[n + HSZ]));
    float gg = tanhf(gr[n + 2 * HSZ]);
    float o  = 1.f / (1.f + expf(-gr[n + 3 * HSZ]));
    float c2 = f * c[idx] + i * gg;
    c[idx] = c2;
    h[idx] = o * tanhf(c2);
}

// ---------------------------------------------------------------------------
// Final layer: y = tanh(y2 @ fc2c_w^T + b), write to out[b, t, :]
// one warp per row (computes both outputs)
// ---------------------------------------------------------------------------
__global__ __launch_bounds__(256)
void fc2c_kernel(const float* __restrict__ y2, const float* __restrict__ w,
                 const float* __restrict__ b, float* __restrict__ out, int t)
{
    const int warp = threadIdx.x >> 5, lane = threadIdx.x & 31;
    const int m = blockIdx.x * 8 + warp;
    const float* yr = y2 + (size_t)m * (HSZ / 4);
    float a0 = 0.f, a1 = 0.f;
#pragma unroll
    for (int d = lane; d < HSZ / 4; d += 32) {
        float v = yr[d];
        a0 += v * w[d];
        a1 += v * w[HSZ / 4 + d];
    }
#pragma unroll
    for (int off = 16; off; off >>= 1) {
        a0 += __shfl_down_sync(0xffffffff, a0, off);
        a1 += __shfl_down_sync(0xffffffff, a1, off);
    }
    if (lane == 0) {
        out[(size_t)m * TT * OSZ + t * OSZ + 0] = tanhf(a0 + b[0]);
        out[(size_t)m * TT * OSZ + t * OSZ + 1] = tanhf(a1 + b[1]);
    }
}

__global__ void zero_states()
{
    int idx = blockIdx.x * blockDim.x + threadIdx.x;
    if (idx < BSN * HSZ) {
        g_h1[idx] = 0.f; g_c1[idx] = 0.f; g_h2[idx] = 0.f; g_c2[idx] = 0.f;
    }
}

// ---------------------------------------------------------------------------
extern "C" void kernel_launch(void* const* d_in, const int* in_sizes, int n_in,
                              void* d_out, int out_size)
{
    (void)in_sizes; (void)n_in; (void)out_size;
    const float* encoded = (const float*)d_in[0];
    const float* z       = (const float*)d_in[1];
    const float* q_w     = (const float*)d_in[2];
    const float* k_w     = (const float*)d_in[3];
    const float* v_w     = (const float*)d_in[4];
    const float* q_b     = (const float*)d_in[5];
    const float* k_b     = (const float*)d_in[6];
    const float* v_b     = (const float*)d_in[7];
    const float* out_w   = (const float*)d_in[8];
    const float* out_b   = (const float*)d_in[9];
    const float* fc1_w   = (const float*)d_in[10];
    const float* fc1_b   = (const float*)d_in[11];
    const float* l1_wih  = (const float*)d_in[12];
    const float* l1_whh  = (const float*)d_in[13];
    const float* l1_bih  = (const float*)d_in[14];
    const float* l1_bhh  = (const float*)d_in[15];
    const float* l2_wih  = (const float*)d_in[16];
    const float* l2_whh  = (const float*)d_in[17];
    const float* l2_bih  = (const float*)d_in[18];
    const float* l2_bhh  = (const float*)d_in[19];
    const float* fc2a_w  = (const float*)d_in[20];
    const float* fc2a_b  = (const float*)d_in[21];
    const float* fc2b_w  = (const float*)d_in[22];
    const float* fc2b_b  = (const float*)d_in[23];
    const float* fc2c_w  = (const float*)d_in[24];
    const float* fc2c_b  = (const float*)d_in[25];
    float* out = (float*)d_out;

    float *pK, *pV, *pq, *patt, *pap, *pf1, *pg, *ph1, *pc1, *ph2, *pc2, *py1, *py2;
    cudaGetSymbolAddress((void**)&pK,  g_K);
    cudaGetSymbolAddress((void**)&pV,  g_V);
    cudaGetSymbolAddress((void**)&pq,  g_q);
    cudaGetSymbolAddress((void**)&patt, g_att);
    cudaGetSymbolAddress((void**)&pap, g_attproj);
    cudaGetSymbolAddress((void**)&pf1, g_fc1);
    cudaGetSymbolAddress((void**)&pg,  g_gates);
    cudaGetSymbolAddress((void**)&ph1, g_h1);
    cudaGetSymbolAddress((void**)&pc1, g_c1);
    cudaGetSymbolAddress((void**)&ph2, g_h2);
    cudaGetSymbolAddress((void**)&pc2, g_c2);
    cudaGetSymbolAddress((void**)&py1, g_y1);
    cudaGetSymbolAddress((void**)&py2, g_y2);

    const float qscale = 0.08838834764831845f;  // 1/sqrt(128)

    zero_states<<<(BSN * HSZ + 255) / 256, 256>>>();

    // K/V projections with layout-transforming epilogues
    {
        dim3 grid(HSZ / 64, (BSN * SS) / 128);
        gemm_kernel<3><<<grid, 256>>>(encoded, ESZ, ESZ, k_w, ESZ,
                                      nullptr, 0, 0, nullptr, 0,
                                      k_b, nullptr, pK, HSZ, 0.f);
        gemm_kernel<4><<<grid, 256>>>(encoded, ESZ, ESZ, v_w, ESZ,
                                      nullptr, 0, 0, nullptr, 0,
                                      v_b, nullptr, pV, HSZ, 0.f);
    }

    dim3 gH(HSZ / 64, BSN / 128);          // N=512
    dim3 gG(4 * HSZ / 64, BSN / 128);      // N=2048
    dim3 gA(HSZ / 2 / 64, BSN / 128);      // N=256
    dim3 gB(HSZ / 4 / 64, BSN / 128);      // N=128

    for (int t = 0; t < TT; ++t) {
        // q = (h2 @ q_w^T + q_b) * scale
        gemm_kernel<2><<<gH, 256>>>(ph2, HSZ, HSZ, q_w, HSZ,
                                    nullptr, 0, 0, nullptr, 0,
                                    q_b, nullptr, pq, HSZ, qscale);
        // attention
        attn_kernel<<<BSN * NH, 128>>>(pq, pK, pV, patt);
        // out proj
        gemm_kernel<0><<<gH, 256>>>(patt, HSZ, HSZ, out_w, HSZ,
                                    nullptr, 0, 0, nullptr, 0,
                                    out_b, nullptr, pap, HSZ, 0.f);
        // fc1: lrelu( [att | z_t] @ fc1_w^T + b )
        gemm_kernel<1><<<gH, 256>>>(pap, HSZ, HSZ, fc1_w, HSZ + LSZ,
                                    z + (size_t)t * LSZ, TT * LSZ, LSZ,
                                    fc1_w + HSZ, HSZ + LSZ,
                                    fc1_b, nullptr, pf1, HSZ, 0.f);
        // LSTM1: gates = fc1 @ wih^T + h1 @ whh^T + biases
        gemm_kernel<0><<<gG, 256>>>(pf1, HSZ, HSZ, l1_wih, HSZ,
                                    ph1, HSZ, HSZ, l1_whh, HSZ,
                                    l1_bih, l1_bhh, pg, 4 * HSZ, 0.f);
        lstm_pw<<<(BSN * HSZ) / 256, 256>>>(pg, ph1, pc1);
        // LSTM2
        gemm_kernel<0><<<gG, 256>>>(ph1, HSZ, HSZ, l2_wih, HSZ,
                                    ph2, HSZ, HSZ, l2_whh, HSZ,
                                    l2_bih, l2_bhh, pg, 4 * HSZ, 0.f);
        lstm_pw<<<(BSN * HSZ) / 256, 256>>>(pg, ph2, pc2);
        // fc2 chain
        gemm_kernel<1><<<gA, 256>>>(ph2, HSZ, HSZ, fc2a_w, HSZ,
                                    nullptr, 0, 0, nullptr, 0,
                                    fc2a_b, nullptr, py1, HSZ / 2, 0.f);
        gemm_kernel<1><<<gB, 256>>>(py1, HSZ / 2, HSZ / 2, fc2b_w, HSZ / 2,
                                    nullptr, 0, 0, nullptr, 0,
                                    fc2b_b, nullptr, py2, HSZ / 4, 0.f);
        fc2c_kernel<<<BSN / 8, 256>>>(py2, fc2c_w, fc2c_b, out, t);
    }
}

// round 2
// speedup vs baseline: 1.5448x; 1.5448x over previous
#include <cuda_runtime.h>
#include <math.h>
#include <stdint.h>

// Problem constants
#define HSZ 512
#define ESZ 256
#define LSZ 64
#define OSZ 2
#define NH  4
#define HD  128   // HSZ/NH
#define BSN 1024
#define SS  100
#define TT  30

// ---------------------------------------------------------------------------
// Scratch (device globals; no allocations allowed)
// ---------------------------------------------------------------------------
__device__ float g_K[(size_t)BSN * NH * HD * SS];   // [b,h,d,s]  (transposed)
__device__ float g_V[(size_t)BSN * NH * SS * HD];   // [b,h,s,d]
__device__ float g_q[BSN * HSZ];
__device__ float g_att[BSN * HSZ];
__device__ float g_attproj[BSN * HSZ];
__device__ float g_fc1[BSN * HSZ];
__device__ float g_gates[BSN * 4 * HSZ];
__device__ float g_h1[BSN * HSZ];
__device__ float g_c1[BSN * HSZ];
__device__ float g_h2[BSN * HSZ];   // carry (att_in == h2)
__device__ float g_c2[BSN * HSZ];
__device__ float g_y1[BSN * (HSZ / 2)];
__device__ float g_y2[BSN * (HSZ / 4)];

// ---------------------------------------------------------------------------
// tf32 tensor-core GEMM:  C = act( A1 @ W1^T [+ A2 @ W2^T] + b1 [+ b2] )
// A row-major [M,K1], W row-major [N,K1].  BM=BN=64, BK=16, 128 threads.
// 4 warps in 2x2 grid, each warp computes 32x32 via mma.sync.m16n8k8.tf32.
// Requires M%64==0, N%64==0, K%16==0 at all call sites (true here).
// EPI: 0 plain, 1 leaky-relu(0.2), 2 scale, 3 K-layout write, 4 V-layout write
// ---------------------------------------------------------------------------
__device__ __forceinline__ uint32_t f2tf32(float x) {
    uint32_t u;
    asm("cvt.rna.tf32.f32 %0, %1;" : "=r"(u) : "f"(x));
    return u;
}

#define SMS 20  // smem row stride in floats (pad 16 -> 20: conflict-free frags)

template <int EPI>
__global__ __launch_bounds__(128)
void tgemm(const float* __restrict__ A1, int lda1, int K1,
           const float* __restrict__ W1, int ldw1,
           const float* __restrict__ A2, int lda2, int K2,
           const float* __restrict__ W2, int ldw2,
           const float* __restrict__ b1, const float* __restrict__ b2,
           float* __restrict__ C, int N, float scale)
{
    __shared__ uint32_t As[64 * SMS];
    __shared__ uint32_t Ws[64 * SMS];

    const int tid  = threadIdx.x;
    const int lane = tid & 31;
    const int warp = tid >> 5;
    const int wm = (warp & 1) * 32;
    const int wn = (warp >> 1) * 32;
    const int m0 = blockIdx.y * 64;
    const int n0 = blockIdx.x * 64;

    const int q  = lane >> 2;    // 0..7
    const int r  = lane & 3;     // 0..3

    float acc[2][4][4];
#pragma unroll
    for (int i = 0; i < 2; i++)
#pragma unroll
        for (int j = 0; j < 4; j++)
#pragma unroll
            for (int f = 0; f < 4; f++) acc[i][j][f] = 0.f;

    // global tile load mapping: idx = tid + i*128 -> row = idx>>2, col4 = (idx&3)*4
#pragma unroll 1
    for (int pass = 0; pass < 2; ++pass) {
        const float* A = pass ? A2 : A1;
        const float* W = pass ? W2 : W1;
        const int lda = pass ? lda2 : lda1;
        const int ldw = pass ? ldw2 : ldw1;
        const int K   = pass ? K2 : K1;
        if (K == 0) continue;

        for (int k0 = 0; k0 < K; k0 += 16) {
#pragma unroll
            for (int i = 0; i < 2; ++i) {
                int idx = tid + i * 128;
                int row = idx >> 2;
                int c   = (idx & 3) * 4;
                float4 va = *reinterpret_cast<const float4*>(
                    A + (size_t)(m0 + row) * lda + k0 + c);
                uint4 ua = make_uint4(f2tf32(va.x), f2tf32(va.y),
                                      f2tf32(va.z), f2tf32(va.w));
                *reinterpret_cast<uint4*>(&As[row * SMS + c]) = ua;
                float4 vw = *reinterpret_cast<const float4*>(
                    W + (size_t)(n0 + row) * ldw + k0 + c);
                uint4 uw = make_uint4(f2tf32(vw.x), f2tf32(vw.y),
                                      f2tf32(vw.z), f2tf32(vw.w));
                *reinterpret_cast<uint4*>(&Ws[row * SMS + c]) = uw;
            }
            __syncthreads();

#pragma unroll
            for (int kk = 0; kk < 16; kk += 8) {
                uint32_t af[2][4], bf[4][2];
#pragma unroll
                for (int mi = 0; mi < 2; ++mi) {
                    int mb = wm + mi * 16;
                    af[mi][0] = As[(mb + q) * SMS + kk + r];
                    af[mi][1] = As[(mb + q + 8) * SMS + kk + r];
                    af[mi][2] = As[(mb + q) * SMS + kk + r + 4];
                    af[mi][3] = As[(mb + q + 8) * SMS + kk + r + 4];
                }
#pragma unroll
                for (int ni = 0; ni < 4; ++ni) {
                    int nb = wn + ni * 8;
                    bf[ni][0] = Ws[(nb + q) * SMS + kk + r];
                    bf[ni][1] = Ws[(nb + q) * SMS + kk + r + 4];
                }
#pragma unroll
                for (int mi = 0; mi < 2; ++mi)
#pragma unroll
                    for (int ni = 0; ni < 4; ++ni) {
                        asm volatile(
                            "mma.sync.aligned.m16n8k8.row.col.f32.tf32.tf32.f32 "
                            "{%0,%1,%2,%3}, {%4,%5,%6,%7}, {%8,%9}, {%0,%1,%2,%3};"
                            : "+f"(acc[mi][ni][0]), "+f"(acc[mi][ni][1]),
                              "+f"(acc[mi][ni][2]), "+f"(acc[mi][ni][3])
                            : "r"(af[mi][0]), "r"(af[mi][1]),
                              "r"(af[mi][2]), "r"(af[mi][3]),
                              "r"(bf[ni][0]), "r"(bf[ni][1]));
                    }
            }
            __syncthreads();
        }
    }

    // epilogue: acc[mi][ni]: rows m0+wm+mi*16+q (+8), cols n0+wn+ni*8+r*2 (+1)
#pragma unroll
    for (int mi = 0; mi < 2; ++mi)
#pragma unroll
        for (int ni = 0; ni < 4; ++ni)
#pragma unroll
            for (int f = 0; f < 4; ++f) {
                int m = m0 + wm + mi * 16 + q + (f >> 1) * 8;
                int n = n0 + wn + ni * 8 + r * 2 + (f & 1);
                float v = acc[mi][ni][f];
                if (b1) v += b1[n];
                if (b2) v += b2[n];
                if (EPI == 1) v = (v >= 0.f) ? v : 0.2f * v;
                if (EPI == 2) v *= scale;
                if (EPI <= 2) {
                    C[(size_t)m * N + n] = v;
                } else {
                    int b = m / SS, s = m - b * SS;
                    if (EPI == 3) {
                        // K: [b, h, d, s]
                        C[(size_t)b * HSZ * SS + (size_t)n * SS + s] = v;
                    } else {
                        // V: [b, h, s, d]
                        int h = n >> 7, d = n & 127;
                        C[(size_t)b * HSZ * SS + (size_t)h * SS * HD
                          + (size_t)s * HD + d] = v;
                    }
                }
            }
}

// ---------------------------------------------------------------------------
// Attention: one block per (b,h). q already scaled. K transposed [d,s], V [s,d].
// ---------------------------------------------------------------------------
__global__ __launch_bounds__(128)
void attn_kernel(const float* __restrict__ q, const float* __restrict__ Kt,
                 const float* __restrict__ V, float* __restrict__ att)
{
    __shared__ float qs[HD];
    __shared__ float sc[128];
    __shared__ float red[128];

    const int bh = blockIdx.x;
    const int b = bh >> 2, h = bh & 3;
    const int tid = threadIdx.x;

    qs[tid] = q[(size_t)b * HSZ + h * HD + tid];
    __syncthreads();

    float a = 0.f;
    const float* Kp = Kt + (size_t)bh * HD * SS;
    if (tid < SS) {
#pragma unroll 8
        for (int d = 0; d < HD; ++d) a += qs[d] * Kp[d * SS + tid];
    }
    sc[tid] = a;
    red[tid] = (tid < SS) ? a : -1e30f;
    __syncthreads();
#pragma unroll
    for (int off = 64; off > 0; off >>= 1) {
        if (tid < off) red[tid] = fmaxf(red[tid], red[tid + off]);
        __syncthreads();
    }
    const float mx = red[0];
    __syncthreads();

    float e = (tid < SS) ? expf(sc[tid] - mx) : 0.f;
    sc[tid] = e;
    red[tid] = e;
    __syncthreads();
#pragma unroll
    for (int off = 64; off > 0; off >>= 1) {
        if (tid < off) red[tid] += red[tid + off];
        __syncthreads();
    }
    const float inv = 1.f / red[0];

    float o = 0.f;
    const float* Vp = V + (size_t)bh * SS * HD + tid;
#pragma unroll 4
    for (int s = 0; s < SS; ++s) o += sc[s] * Vp[(size_t)s * HD];
    att[(size_t)b * HSZ + h * HD + tid] = o * inv;
}

// ---------------------------------------------------------------------------
// LSTM pointwise
// ---------------------------------------------------------------------------
__global__ void lstm_pw(const float* __restrict__ g,
                        float* __restrict__ h, float* __restrict__ c)
{
    int idx = blockIdx.x * blockDim.x + threadIdx.x;
    int m = idx >> 9;
    int n = idx & 511;
    const float* gr = g + (size_t)m * (4 * HSZ);
    float i  = 1.f / (1.f + expf(-gr[n]));
    float f  = 1.f / (1.f + expf(-gr[n + HSZ]));
    float gg = tanhf(gr[n + 2 * HSZ]);
    float o  = 1.f / (1.f + expf(-gr[n + 3 * HSZ]));
    float c2 = f * c[idx] + i * gg;
    c[idx] = c2;
    h[idx] = o * tanhf(c2);
}

// ---------------------------------------------------------------------------
// Final tiny layer
// ---------------------------------------------------------------------------
__global__ __launch_bounds__(256)
void fc2c_kernel(const float* __restrict__ y2, const float* __restrict__ w,
                 const float* __restrict__ b, float* __restrict__ out, int t)
{
    const int warp = threadIdx.x >> 5, lane = threadIdx.x & 31;
    const int m = blockIdx.x * 8 + warp;
    const float* yr = y2 + (size_t)m * (HSZ / 4);
    float a0 = 0.f, a1 = 0.f;
#pragma unroll
    for (int d = lane; d < HSZ / 4; d += 32) {
        float v = yr[d];
        a0 += v * w[d];
        a1 += v * w[HSZ / 4 + d];
    }
#pragma unroll
    for (int off = 16; off; off >>= 1) {
        a0 += __shfl_down_sync(0xffffffff, a0, off);
        a1 += __shfl_down_sync(0xffffffff, a1, off);
    }
    if (lane == 0) {
        out[(size_t)m * TT * OSZ + t * OSZ + 0] = tanhf(a0 + b[0]);
        out[(size_t)m * TT * OSZ + t * OSZ + 1] = tanhf(a1 + b[1]);
    }
}

__global__ void zero_states()
{
    int idx = blockIdx.x * blockDim.x + threadIdx.x;
    if (idx < BSN * HSZ) {
        g_h1[idx] = 0.f; g_c1[idx] = 0.f; g_h2[idx] = 0.f; g_c2[idx] = 0.f;
    }
}

// ---------------------------------------------------------------------------
extern "C" void kernel_launch(void* const* d_in, const int* in_sizes, int n_in,
                              void* d_out, int out_size)
{
    (void)in_sizes; (void)n_in; (void)out_size;
    const float* encoded = (const float*)d_in[0];
    const float* z       = (const float*)d_in[1];
    const float* q_w     = (const float*)d_in[2];
    const float* k_w     = (const float*)d_in[3];
    const float* v_w     = (const float*)d_in[4];
    const float* q_b     = (const float*)d_in[5];
    const float* k_b     = (const float*)d_in[6];
    const float* v_b     = (const float*)d_in[7];
    const float* out_w   = (const float*)d_in[8];
    const float* out_b   = (const float*)d_in[9];
    const float* fc1_w   = (const float*)d_in[10];
    const float* fc1_b   = (const float*)d_in[11];
    const float* l1_wih  = (const float*)d_in[12];
    const float* l1_whh  = (const float*)d_in[13];
    const float* l1_bih  = (const float*)d_in[14];
    const float* l1_bhh  = (const float*)d_in[15];
    const float* l2_wih  = (const float*)d_in[16];
    const float* l2_whh  = (const float*)d_in[17];
    const float* l2_bih  = (const float*)d_in[18];
    const float* l2_bhh  = (const float*)d_in[19];
    const float* fc2a_w  = (const float*)d_in[20];
    const float* fc2a_b  = (const float*)d_in[21];
    const float* fc2b_w  = (const float*)d_in[22];
    const float* fc2b_b  = (const float*)d_in[23];
    const float* fc2c_w  = (const float*)d_in[24];
    const float* fc2c_b  = (const float*)d_in[25];
    float* out = (float*)d_out;

    float *pK, *pV, *pq, *patt, *pap, *pf1, *pg, *ph1, *pc1, *ph2, *pc2, *py1, *py2;
    cudaGetSymbolAddress((void**)&pK,  g_K);
    cudaGetSymbolAddress((void**)&pV,  g_V);
    cudaGetSymbolAddress((void**)&pq,  g_q);
    cudaGetSymbolAddress((void**)&patt, g_att);
    cudaGetSymbolAddress((void**)&pap, g_attproj);
    cudaGetSymbolAddress((void**)&pf1, g_fc1);
    cudaGetSymbolAddress((void**)&pg,  g_gates);
    cudaGetSymbolAddress((void**)&ph1, g_h1);
    cudaGetSymbolAddress((void**)&pc1, g_c1);
    cudaGetSymbolAddress((void**)&ph2, g_h2);
    cudaGetSymbolAddress((void**)&pc2, g_c2);
    cudaGetSymbolAddress((void**)&py1, g_y1);
    cudaGetSymbolAddress((void**)&py2, g_y2);

    const float qscale = 0.08838834764831845f;  // 1/sqrt(128)

    zero_states<<<(BSN * HSZ + 255) / 256, 256>>>();

    // K/V projections with layout-transforming epilogues
    {
        dim3 grid(HSZ / 64, (BSN * SS) / 64);
        tgemm<3><<<grid, 128>>>(encoded, ESZ, ESZ, k_w, ESZ,
                                nullptr, 0, 0, nullptr, 0,
                                k_b, nullptr, pK, HSZ, 0.f);
        tgemm<4><<<grid, 128>>>(encoded, ESZ, ESZ, v_w, ESZ,
                                nullptr, 0, 0, nullptr, 0,
                                v_b, nullptr, pV, HSZ, 0.f);
    }

    dim3 gH(HSZ / 64, BSN / 64);           // N=512
    dim3 gG(4 * HSZ / 64, BSN / 64);       // N=2048
    dim3 gA(HSZ / 2 / 64, BSN / 64);       // N=256
    dim3 gB(HSZ / 4 / 64, BSN / 64);       // N=128

    for (int t = 0; t < TT; ++t) {
        tgemm<2><<<gH, 128>>>(ph2, HSZ, HSZ, q_w, HSZ,
                              nullptr, 0, 0, nullptr, 0,
                              q_b, nullptr, pq, HSZ, qscale);
        attn_kernel<<<BSN * NH, 128>>>(pq, pK, pV, patt);
        tgemm<0><<<gH, 128>>>(patt, HSZ, HSZ, out_w, HSZ,
                              nullptr, 0, 0, nullptr, 0,
                              out_b, nullptr, pap, HSZ, 0.f);
        tgemm<1><<<gH, 128>>>(pap, HSZ, HSZ, fc1_w, HSZ + LSZ,
                              z + (size_t)t * LSZ, TT * LSZ, LSZ,
                              fc1_w + HSZ, HSZ + LSZ,
                              fc1_b, nullptr, pf1, HSZ, 0.f);
        tgemm<0><<<gG, 128>>>(pf1, HSZ, HSZ, l1_wih, HSZ,
                              ph1, HSZ, HSZ, l1_whh, HSZ,
                              l1_bih, l1_bhh, pg, 4 * HSZ, 0.f);
        lstm_pw<<<(BSN * HSZ) / 256, 256>>>(pg, ph1, pc1);
        tgemm<0><<<gG, 128>>>(ph1, HSZ, HSZ, l2_wih, HSZ,
                              ph2, HSZ, HSZ, l2_whh, HSZ,
                              l2_bih, l2_bhh, pg, 4 * HSZ, 0.f);
        lstm_pw<<<(BSN * HSZ) / 256, 256>>>(pg, ph2, pc2);
        tgemm<1><<<gA, 128>>>(ph2, HSZ, HSZ, fc2a_w, HSZ,
                              nullptr, 0, 0, nullptr, 0,
                              fc2a_b, nullptr, py1, HSZ / 2, 0.f);
        tgemm<1><<<gB, 128>>>(py1, HSZ / 2, HSZ / 2, fc2b_w, HSZ / 2,
                              nullptr, 0, 0, nullptr, 0,
                              fc2b_b, nullptr, py2, HSZ / 4, 0.f);
        fc2c_kernel<<<BSN / 8, 256>>>(py2, fc2c_w, fc2c_b, out, t);
    }
}

// round 3
// speedup vs baseline: 2.2603x; 1.4632x over previous
#include <cuda_runtime.h>
#include <math.h>
#include <stdint.h>

// Problem constants
#define HSZ 512
#define ESZ 256
#define LSZ 64
#define OSZ 2
#define NH  4
#define HD  128   // HSZ/NH
#define BSN 1024
#define SS  100
#define TT  30

// ---------------------------------------------------------------------------
// Scratch (device globals; no allocations allowed)
// ---------------------------------------------------------------------------
__device__ float g_K[(size_t)BSN * NH * HD * SS];   // [b,h,d,s]  (transposed)
__device__ float g_V[(size_t)BSN * NH * SS * HD];   // [b,h,s,d]
__device__ float g_q[BSN * HSZ];
__device__ float g_att[BSN * HSZ];
__device__ float g_attproj[BSN * HSZ];
__device__ float g_fc1[BSN * HSZ];
__device__ float g_gates[BSN * 4 * HSZ];
__device__ float g_h1[BSN * HSZ];
__device__ float g_c1[BSN * HSZ];
__device__ float g_h2[BSN * HSZ];   // carry (att_in == h2)
__device__ float g_c2[BSN * HSZ];
__device__ float g_y1[BSN * (HSZ / 2)];
__device__ float g_y2[BSN * (HSZ / 4)];

__device__ __forceinline__ uint32_t f2tf32(float x) {
    uint32_t u;
    asm("cvt.rna.tf32.f32 %0, %1;" : "=r"(u) : "f"(x));
    return u;
}

__device__ __forceinline__ void cp16(uint32_t dst, const float* src) {
    asm volatile("cp.async.cg.shared.global [%0], [%1], 16;"
                 :: "r"(dst), "l"(src));
}

#define STR 36  // smem row stride in floats (32 + 4 pad: conflict-free frags)

// ---------------------------------------------------------------------------
// tf32 tensor-core GEMM, cp.async double-buffered:
//   C = act( A1 @ W1^T [+ A2 @ W2^T] + b1 [+ b2] )
// A row-major [M,K], W row-major [N,K].  BN=64, BK=32.
// BM=128: 256 thr, 8 warps (4 along M, 2 along N), warp tile 32x32.
// BM=64 : 128 thr, 4 warps (2 along M, 2 along N), warp tile 32x32.
// Requires M%BM==0, N%64==0, K%32==0 (true at all call sites).
// EPI: 0 plain, 1 leaky-relu(0.2), 2 scale, 3 K-layout write, 4 V-layout write
// ---------------------------------------------------------------------------
template <int EPI, int BM>
__global__ __launch_bounds__(BM * 2)
void tgemm(const float* __restrict__ A1, int lda1, int K1,
           const float* __restrict__ W1, int ldw1,
           const float* __restrict__ A2, int lda2, int K2,
           const float* __restrict__ W2, int ldw2,
           const float* __restrict__ b1, const float* __restrict__ b2,
           float* __restrict__ C, int N, float scale)
{
    constexpr int T  = BM * 2;          // threads
    constexpr int WM = BM / 32;         // warps along M

    extern __shared__ float smem[];
    float* Asm = smem;                   // 2 * BM * STR
    float* Wsm = smem + 2 * BM * STR;    // 2 * 64 * STR

    const int tid  = threadIdx.x;
    const int lane = tid & 31;
    const int warp = tid >> 5;
    const int wm = (warp % WM) * 32;
    const int wn = (warp / WM) * 32;
    const int m0 = blockIdx.y * BM;
    const int n0 = blockIdx.x * 64;

    const int q = lane >> 2;    // 0..7
    const int r = lane & 3;     // 0..3

    const uint32_t As_b = (uint32_t)__cvta_generic_to_shared(Asm);
    const uint32_t Ws_b = (uint32_t)__cvta_generic_to_shared(Wsm);

    float acc[2][4][4];
#pragma unroll
    for (int i = 0; i < 2; i++)
#pragma unroll
        for (int j = 0; j < 4; j++)
#pragma unroll
            for (int f = 0; f < 4; f++) acc[i][j][f] = 0.f;

#pragma unroll 1
    for (int pass = 0; pass < 2; ++pass) {
        const float* A = pass ? A2 : A1;
        const float* W = pass ? W2 : W1;
        const int lda = pass ? lda2 : lda1;
        const int ldw = pass ? ldw2 : ldw1;
        const int K   = pass ? K2 : K1;
        if (K == 0) continue;

        auto load_tile = [&](int k0, int buf) {
            // A tile: BM rows x 8 float4
#pragma unroll
            for (int i = tid; i < BM * 8; i += T) {
                int row = i >> 3, col = (i & 7) * 4;
                cp16(As_b + (uint32_t)(buf * BM * STR + row * STR + col) * 4,
                     A + (size_t)(m0 + row) * lda + k0 + col);
            }
            // W tile: 64 rows x 8 float4
#pragma unroll
            for (int i = tid; i < 64 * 8; i += T) {
                int row = i >> 3, col = (i & 7) * 4;
                cp16(Ws_b + (uint32_t)(buf * 64 * STR + row * STR + col) * 4,
                     W + (size_t)(n0 + row) * ldw + k0 + col);
            }
        };

        const int nk = K >> 5;
        load_tile(0, 0);
        asm volatile("cp.async.commit_group;" ::: "memory");

#pragma unroll 1
        for (int kt = 0; kt < nk; ++kt) {
            if (kt + 1 < nk) load_tile((kt + 1) << 5, (kt + 1) & 1);
            asm volatile("cp.async.commit_group;" ::: "memory");
            asm volatile("cp.async.wait_group 1;" ::: "memory");
            __syncthreads();

            const float* Ab = Asm + (kt & 1) * BM * STR;
            const float* Wb = Wsm + (kt & 1) * 64 * STR;

#pragma unroll
            for (int kk = 0; kk < 32; kk += 8) {
                uint32_t af[2][4], bf[4][2];
#pragma unroll
                for (int mi = 0; mi < 2; ++mi) {
                    int mb = wm + mi * 16;
                    af[mi][0] = f2tf32(Ab[(mb + q) * STR + kk + r]);
                    af[mi][1] = f2tf32(Ab[(mb + q + 8) * STR + kk + r]);
                    af[mi][2] = f2tf32(Ab[(mb + q) * STR + kk + r + 4]);
                    af[mi][3] = f2tf32(Ab[(mb + q + 8) * STR + kk + r + 4]);
                }
#pragma unroll
                for (int ni = 0; ni < 4; ++ni) {
                    int nb = wn + ni * 8;
                    bf[ni][0] = f2tf32(Wb[(nb + q) * STR + kk + r]);
                    bf[ni][1] = f2tf32(Wb[(nb + q) * STR + kk + r + 4]);
                }
#pragma unroll
                for (int mi = 0; mi < 2; ++mi)
#pragma unroll
                    for (int ni = 0; ni < 4; ++ni) {
                        asm volatile(
                            "mma.sync.aligned.m16n8k8.row.col.f32.tf32.tf32.f32 "
                            "{%0,%1,%2,%3}, {%4,%5,%6,%7}, {%8,%9}, {%0,%1,%2,%3};"
                            : "+f"(acc[mi][ni][0]), "+f"(acc[mi][ni][1]),
                              "+f"(acc[mi][ni][2]), "+f"(acc[mi][ni][3])
                            : "r"(af[mi][0]), "r"(af[mi][1]),
                              "r"(af[mi][2]), "r"(af[mi][3]),
                              "r"(bf[ni][0]), "r"(bf[ni][1]));
                    }
            }
            __syncthreads();
        }
    }

    // epilogue
#pragma unroll
    for (int mi = 0; mi < 2; ++mi)
#pragma unroll
        for (int ni = 0; ni < 4; ++ni)
#pragma unroll
            for (int f = 0; f < 4; ++f) {
                int m = m0 + wm + mi * 16 + q + (f >> 1) * 8;
                int n = n0 + wn + ni * 8 + r * 2 + (f & 1);
                float v = acc[mi][ni][f];
                if (b1) v += b1[n];
                if (b2) v += b2[n];
                if (EPI == 1) v = (v >= 0.f) ? v : 0.2f * v;
                if (EPI == 2) v *= scale;
                if (EPI <= 2) {
                    C[(size_t)m * N + n] = v;
                } else {
                    int b = m / SS, s = m - b * SS;
                    if (EPI == 3) {
                        // K: [b, h, d, s]
                        C[(size_t)b * HSZ * SS + (size_t)n * SS + s] = v;
                    } else {
                        // V: [b, h, s, d]
                        int h = n >> 7, d = n & 127;
                        C[(size_t)b * HSZ * SS + (size_t)h * SS * HD
                          + (size_t)s * HD + d] = v;
                    }
                }
            }
}

// ---------------------------------------------------------------------------
// Attention: one block per (b,h). q already scaled. K transposed [d,s], V [s,d].
// ---------------------------------------------------------------------------
__global__ __launch_bounds__(128)
void attn_kernel(const float* __restrict__ q, const float* __restrict__ Kt,
                 const float* __restrict__ V, float* __restrict__ att)
{
    __shared__ float qs[HD];
    __shared__ float sc[128];
    __shared__ float red[128];

    const int bh = blockIdx.x;
    const int b = bh >> 2, h = bh & 3;
    const int tid = threadIdx.x;

    qs[tid] = q[(size_t)b * HSZ + h * HD + tid];
    __syncthreads();

    float a = 0.f;
    const float* Kp = Kt + (size_t)bh * HD * SS;
    if (tid < SS) {
#pragma unroll 8
        for (int d = 0; d < HD; ++d) a += qs[d] * Kp[d * SS + tid];
    }
    sc[tid] = a;
    red[tid] = (tid < SS) ? a : -1e30f;
    __syncthreads();
#pragma unroll
    for (int off = 64; off > 0; off >>= 1) {
        if (tid < off) red[tid] = fmaxf(red[tid], red[tid + off]);
        __syncthreads();
    }
    const float mx = red[0];
    __syncthreads();

    float e = (tid < SS) ? expf(sc[tid] - mx) : 0.f;
    sc[tid] = e;
    red[tid] = e;
    __syncthreads();
#pragma unroll
    for (int off = 64; off > 0; off >>= 1) {
        if (tid < off) red[tid] += red[tid + off];
        __syncthreads();
    }
    const float inv = 1.f / red[0];

    float o = 0.f;
    const float* Vp = V + (size_t)bh * SS * HD + tid;
#pragma unroll 4
    for (int s = 0; s < SS; ++s) o += sc[s] * Vp[(size_t)s * HD];
    att[(size_t)b * HSZ + h * HD + tid] = o * inv;
}

// ---------------------------------------------------------------------------
// LSTM pointwise
// ---------------------------------------------------------------------------
__global__ void lstm_pw(const float* __restrict__ g,
                        float* __restrict__ h, float* __restrict__ c)
{
    int idx = blockIdx.x * blockDim.x + threadIdx.x;
    int m = idx >> 9;
    int n = idx & 511;
    const float* gr = g + (size_t)m * (4 * HSZ);
    float i  = 1.f / (1.f + expf(-gr[n]));
    float f  = 1.f / (1.f + expf(-gr[n + HSZ]));
    float gg = tanhf(gr[n + 2 * HSZ]);
    float o  = 1.f / (1.f + expf(-gr[n + 3 * HSZ]));
    float c2 = f * c[idx] + i * gg;
    c[idx] = c2;
    h[idx] = o * tanhf(c2);
}

// ---------------------------------------------------------------------------
// Final tiny layer
// ---------------------------------------------------------------------------
__global__ __launch_bounds__(256)
void fc2c_kernel(const float* __restrict__ y2, const float* __restrict__ w,
                 const float* __restrict__ b, float* __restrict__ out, int t)
{
    const int warp = threadIdx.x >> 5, lane = threadIdx.x & 31;
    const int m = blockIdx.x * 8 + warp;
    const float* yr = y2 + (size_t)m * (HSZ / 4);
    float a0 = 0.f, a1 = 0.f;
#pragma unroll
    for (int d = lane; d < HSZ / 4; d += 32) {
        float v = yr[d];
        a0 += v * w[d];
        a1 += v * w[HSZ / 4 + d];
    }
#pragma unroll
    for (int off = 16; off; off >>= 1) {
        a0 += __shfl_down_sync(0xffffffff, a0, off);
        a1 += __shfl_down_sync(0xffffffff, a1, off);
    }
    if (lane == 0) {
        out[(size_t)m * TT * OSZ + t * OSZ + 0] = tanhf(a0 + b[0]);
        out[(size_t)m * TT * OSZ + t * OSZ + 1] = tanhf(a1 + b[1]);
    }
}

__global__ void zero_states()
{
    int idx = blockIdx.x * blockDim.x + threadIdx.x;
    if (idx < BSN * HSZ) {
        g_h1[idx] = 0.f; g_c1[idx] = 0.f; g_h2[idx] = 0.f; g_c2[idx] = 0.f;
    }
}

// ---------------------------------------------------------------------------
extern "C" void kernel_launch(void* const* d_in, const int* in_sizes, int n_in,
                              void* d_out, int out_size)
{
    (void)in_sizes; (void)n_in; (void)out_size;
    const float* encoded = (const float*)d_in[0];
    const float* z       = (const float*)d_in[1];
    const float* q_w     = (const float*)d_in[2];
    const float* k_w     = (const float*)d_in[3];
    const float* v_w     = (const float*)d_in[4];
    const float* q_b     = (const float*)d_in[5];
    const float* k_b     = (const float*)d_in[6];
    const float* v_b     = (const float*)d_in[7];
    const float* out_w   = (const float*)d_in[8];
    const float* out_b   = (const float*)d_in[9];
    const float* fc1_w   = (const float*)d_in[10];
    const float* fc1_b   = (const float*)d_in[11];
    const float* l1_wih  = (const float*)d_in[12];
    const float* l1_whh  = (const float*)d_in[13];
    const float* l1_bih  = (const float*)d_in[14];
    const float* l1_bhh  = (const float*)d_in[15];
    const float* l2_wih  = (const float*)d_in[16];
    const float* l2_whh  = (const float*)d_in[17];
    const float* l2_bih  = (const float*)d_in[18];
    const float* l2_bhh  = (const float*)d_in[19];
    const float* fc2a_w  = (const float*)d_in[20];
    const float* fc2a_b  = (const float*)d_in[21];
    const float* fc2b_w  = (const float*)d_in[22];
    const float* fc2b_b  = (const float*)d_in[23];
    const float* fc2c_w  = (const float*)d_in[24];
    const float* fc2c_b  = (const float*)d_in[25];
    float* out = (float*)d_out;

    float *pK, *pV, *pq, *patt, *pap, *pf1, *pg, *ph1, *pc1, *ph2, *pc2, *py1, *py2;
    cudaGetSymbolAddress((void**)&pK,  g_K);
    cudaGetSymbolAddress((void**)&pV,  g_V);
    cudaGetSymbolAddress((void**)&pq,  g_q);
    cudaGetSymbolAddress((void**)&patt, g_att);
    cudaGetSymbolAddress((void**)&pap, g_attproj);
    cudaGetSymbolAddress((void**)&pf1, g_fc1);
    cudaGetSymbolAddress((void**)&pg,  g_gates);
    cudaGetSymbolAddress((void**)&ph1, g_h1);
    cudaGetSymbolAddress((void**)&pc1, g_c1);
    cudaGetSymbolAddress((void**)&ph2, g_h2);
    cudaGetSymbolAddress((void**)&pc2, g_c2);
    cudaGetSymbolAddress((void**)&py1, g_y1);
    cudaGetSymbolAddress((void**)&py2, g_y2);

    const size_t SM128 = (size_t)(2 * 128 + 2 * 64) * STR * sizeof(float); // 55296
    const size_t SM64  = (size_t)(2 * 64 + 2 * 64) * STR * sizeof(float);  // 36864

    cudaFuncSetAttribute(tgemm<0, 128>, cudaFuncAttributeMaxDynamicSharedMemorySize, (int)SM128);
    cudaFuncSetAttribute(tgemm<3, 128>, cudaFuncAttributeMaxDynamicSharedMemorySize, (int)SM128);
    cudaFuncSetAttribute(tgemm<4, 128>, cudaFuncAttributeMaxDynamicSharedMemorySize, (int)SM128);

    const float qscale = 0.08838834764831845f;  // 1/sqrt(128)

    zero_states<<<(BSN * HSZ + 255) / 256, 256>>>();

    // K/V projections with layout-transforming epilogues
    {
        dim3 grid(HSZ / 64, (BSN * SS) / 128);
        tgemm<3, 128><<<grid, 256, SM128>>>(encoded, ESZ, ESZ, k_w, ESZ,
                                            nullptr, 0, 0, nullptr, 0,
                                            k_b, nullptr, pK, HSZ, 0.f);
        tgemm<4, 128><<<grid, 256, SM128>>>(encoded, ESZ, ESZ, v_w, ESZ,
                                            nullptr, 0, 0, nullptr, 0,
                                            v_b, nullptr, pV, HSZ, 0.f);
    }

    dim3 gH(HSZ / 64, BSN / 64);            // 8 x 16 = 128 CTAs (BM=64)
    dim3 gG(4 * HSZ / 64, BSN / 128);       // 32 x 8 = 256 CTAs (BM=128)
    dim3 gA(HSZ / 2 / 64, BSN / 64);        // 4 x 16
    dim3 gB(HSZ / 4 / 64, BSN / 64);        // 2 x 16

    for (int t = 0; t < TT; ++t) {
        tgemm<2, 64><<<gH, 128, SM64>>>(ph2, HSZ, HSZ, q_w, HSZ,
                                        nullptr, 0, 0, nullptr, 0,
                                        q_b, nullptr, pq, HSZ, qscale);
        attn_kernel<<<BSN * NH, 128>>>(pq, pK, pV, patt);
        tgemm<0, 64><<<gH, 128, SM64>>>(patt, HSZ, HSZ, out_w, HSZ,
                                        nullptr, 0, 0, nullptr, 0,
                                        out_b, nullptr, pap, HSZ, 0.f);
        tgemm<1, 64><<<gH, 128, SM64>>>(pap, HSZ, HSZ, fc1_w, HSZ + LSZ,
                                        z + (size_t)t * LSZ, TT * LSZ, LSZ,
                                        fc1_w + HSZ, HSZ + LSZ,
                                        fc1_b, nullptr, pf1, HSZ, 0.f);
        tgemm<0, 128><<<gG, 256, SM128>>>(pf1, HSZ, HSZ, l1_wih, HSZ,
                                          ph1, HSZ, HSZ, l1_whh, HSZ,
                                          l1_bih, l1_bhh, pg, 4 * HSZ, 0.f);
        lstm_pw<<<(BSN * HSZ) / 256, 256>>>(pg, ph1, pc1);
        tgemm<0, 128><<<gG, 256, SM128>>>(ph1, HSZ, HSZ, l2_wih, HSZ,
                                          ph2, HSZ, HSZ, l2_whh, HSZ,
                                          l2_bih, l2_bhh, pg, 4 * HSZ, 0.f);
        lstm_pw<<<(BSN * HSZ) / 256, 256>>>(pg, ph2, pc2);
        tgemm<1, 64><<<gA, 128, SM64>>>(ph2, HSZ, HSZ, fc2a_w, HSZ,
                                        nullptr, 0, 0, nullptr, 0,
                                        fc2a_b, nullptr, py1, HSZ / 2, 0.f);
        tgemm<1, 64><<<gB, 128, SM64>>>(py1, HSZ / 2, HSZ / 2, fc2b_w, HSZ / 2,
                                        nullptr, 0, 0, nullptr, 0,
                                        fc2b_b, nullptr, py2, HSZ / 4, 0.f);
        fc2c_kernel<<<BSN / 8, 256>>>(py2, fc2c_w, fc2c_b, out, t);
    }
}